// round 12
// baseline (speedup 1.0000x reference)
#include <cuda_runtime.h>
#include <cstdint>

#define NNODES 50000
#define ERAW   800000
#define ETOT   850000
#define NEG_SLOPE 0.2f
#define NSCAN_BLK 196            // ceil(50000/256)

// Layer dims (HCP = HC + 16 extra cols: [h(HC) | als(8) | ald(8)]):
//  L1: K=128 H=7 C=16 HC=112 HCP=128
//  L2: K=112 H=6 C=16 HC=96  HCP=112
//  L3: K=96  H=6 C=40 HC=240 HCP=256

// ---------------- scratch (device globals; no allocation allowed) ----------------
__device__ float g_bufX[(size_t)NNODES * 112];   // dense layer output / next input
__device__ float g_bufH[(size_t)NNODES * 256];   // GEMM output rows [h|als|ald]
__device__ float g_Bp  [24576];                  // packed B' (max 96*256)
__device__ int   g_edges[2 * ERAW];
__device__ int   g_deg   [NNODES];
__device__ int   g_offs  [NNODES + 1];
__device__ int   g_cursor[NNODES];
__device__ int   g_csrsrc[ETOT];
__device__ int   g_bsum  [NSCAN_BLK];
__device__ int   g_boff  [NSCAN_BLK];
__device__ int   g_is64;

static inline int cdiv(int a, int b) { return (a + b - 1) / b; }

// ---------------- edge-index width detect ----------------
__global__ void detect_kernel(const int* __restrict__ ei) {
    __shared__ int any;
    if (threadIdx.x == 0) any = 0;
    __syncthreads();
    int bad = 0;
    for (int i = threadIdx.x; i < 2048; i += blockDim.x)
        if (ei[2 * i + 1] != 0) bad = 1;
    if (bad) any = 1;
    __syncthreads();
    if (threadIdx.x == 0) g_is64 = any ? 0 : 1;
}

__global__ void zero_deg_kernel() {
    int i = blockIdx.x * blockDim.x + threadIdx.x;
    if (i < NNODES) g_deg[i] = 0;
}

// convert + histogram in one edge pass
__global__ void convert_hist_kernel(const int* __restrict__ ei) {
    int e = blockIdx.x * blockDim.x + threadIdx.x;
    if (e >= ETOT) return;
    int d;
    if (e < ERAW) {
        int s = g_is64 ? ei[2 * e] : ei[e];
        d     = g_is64 ? ei[2 * (ERAW + e)] : ei[ERAW + e];
        g_edges[e] = s;
        g_edges[ERAW + e] = d;
    } else {
        d = e - ERAW;
    }
    atomicAdd(&g_deg[d], 1);
}

// ---------------- multi-block exclusive scan of g_deg -> g_offs ----------------
__global__ void scan_phase1_kernel() {      // grid = NSCAN_BLK, block = 256
    __shared__ int sh[8];
    int i = blockIdx.x * 256 + threadIdx.x;
    int v = (i < NNODES) ? g_deg[i] : 0;
#pragma unroll
    for (int off = 16; off >= 1; off >>= 1) v += __shfl_xor_sync(0xffffffffu, v, off);
    if ((threadIdx.x & 31) == 0) sh[threadIdx.x >> 5] = v;
    __syncthreads();
    if (threadIdx.x == 0) {
        int s = 0;
#pragma unroll
        for (int w = 0; w < 8; w++) s += sh[w];
        g_bsum[blockIdx.x] = s;
    }
}

__global__ void scan_phase2_kernel() {      // 1 block, 256 threads
    __shared__ int sh[256];
    int t = threadIdx.x;
    int v = (t < NSCAN_BLK) ? g_bsum[t] : 0;
    sh[t] = v;
    __syncthreads();
    for (int off = 1; off < 256; off <<= 1) {
        int u = (t >= off) ? sh[t - off] : 0;
        __syncthreads();
        sh[t] += u;
        __syncthreads();
    }
    if (t < NSCAN_BLK) g_boff[t] = sh[t] - v;   // exclusive
}

__global__ void scan_phase3_kernel() {      // grid = NSCAN_BLK, block = 256
    __shared__ int sh[256];
    int t = threadIdx.x;
    int i = blockIdx.x * 256 + t;
    int v = (i < NNODES) ? g_deg[i] : 0;
    sh[t] = v;
    __syncthreads();
    for (int off = 1; off < 256; off <<= 1) {
        int u = (t >= off) ? sh[t - off] : 0;
        __syncthreads();
        sh[t] += u;
        __syncthreads();
    }
    if (i < NNODES) {
        int o = g_boff[blockIdx.x] + sh[t] - v;  // exclusive
        g_offs[i] = o;
        g_cursor[i] = o;
    }
    if (i == NNODES - 1) g_offs[NNODES] = ETOT;
}

__global__ void scatter_kernel() {
    int e = blockIdx.x * blockDim.x + threadIdx.x;
    if (e >= ETOT) return;
    int s, d;
    if (e < ERAW) { s = g_edges[e]; d = g_edges[ERAW + e]; }
    else          { s = d = e - ERAW; }
    int pos = atomicAdd(&g_cursor[d], 1);
    g_csrsrc[pos] = s;
}

// ---------------- pack B' = [W | W*a_src | W*a_dst(pad to 8 each)] ----------------
template <int K, int H, int C>
__global__ void pack_kernel(const float* __restrict__ W, const float* __restrict__ as,
                            const float* __restrict__ ad, float* __restrict__ Bp) {
    const int HC = H * C, HCP = HC + 16;
    int idx = blockIdx.x * blockDim.x + threadIdx.x;
    if (idx >= K * HCP) return;
    int k = idx / HCP, col = idx - k * HCP;
    float v = 0.f;
    if (col < HC) {
        v = W[(size_t)k * HC + col];
    } else {
        int hc = col - HC;
        int h = hc & 7;
        const float* a = (hc < 8) ? as : ad;
        if (h < H) {
#pragma unroll 4
            for (int c = 0; c < C; c++)
                v += W[(size_t)k * HC + h * C + c] * a[h * C + c];
        }
    }
    Bp[idx] = v;
}

// ---------------- tf32 helpers ----------------
__device__ __forceinline__ uint32_t f2tf32(float f) {
    uint32_t u;
    asm("cvt.rna.tf32.f32 %0, %1;" : "=r"(u) : "f"(f));
    return u;
}
__device__ __forceinline__ void split_tf32(float f, uint32_t& hi, uint32_t& lo) {
    hi = f2tf32(f);
    lo = f2tf32(f - __uint_as_float(hi));
}

#define MMA_TF32(c, a, b)                                                       \
    asm volatile("mma.sync.aligned.m16n8k8.row.col.f32.tf32.tf32.f32 "          \
                 "{%0,%1,%2,%3},{%4,%5,%6,%7},{%8,%9},{%0,%1,%2,%3};"           \
                 : "+f"((c)[0]), "+f"((c)[1]), "+f"((c)[2]), "+f"((c)[3])       \
                 : "r"((a)[0]), "r"((a)[1]), "r"((a)[2]), "r"((a)[3]),          \
                   "r"((b)[0]), "r"((b)[1]))

// ---------------- GEMM: C[M,N] = A[M,K] @ B[K,N], tf32 tensor, 3x split ------------
// 128x64 block tile, BK=16, 8 warps (4x2), 32x32 warp tile = 2x4 m16n8k8 frags.
// K must be a multiple of 16 (true: 128/112/96). N arbitrary (guarded).
__global__ void __launch_bounds__(256) gemm_tf32_kernel(const float* __restrict__ A,
                                                        const float* __restrict__ B,
                                                        float* __restrict__ Cmat,
                                                        int M, int K, int N) {
    // A planes: [m][k] stride 20 (gcd(20,32)=4 -> fragment loads conflict-free)
    __shared__ uint32_t As_hi[128][20], As_lo[128][20];
    // B planes: [k][n] stride 72 (row shift 8 banks -> conflict-free)
    __shared__ uint32_t Bs_hi[16][72], Bs_lo[16][72];

    int tid = threadIdx.x;
    int lane = tid & 31, wid = tid >> 5;
    int row0 = blockIdx.y * 128, col0 = blockIdx.x * 64;
    int wm = (wid & 3) * 32, wn = (wid >> 2) * 32;
    int q = lane & 3, g = lane >> 2;

    float acc[2][4][4];
#pragma unroll
    for (int mt = 0; mt < 2; mt++)
#pragma unroll
        for (int nt = 0; nt < 4; nt++)
#pragma unroll
            for (int i = 0; i < 4; i++) acc[mt][nt][i] = 0.f;

    for (int k0 = 0; k0 < K; k0 += 16) {
        // ---- load A tile 128x16 (2 float4 per thread), split, store [m][k] ----
#pragma unroll
        for (int l = 0; l < 2; l++) {
            int idx = tid + l * 256;
            int r = idx >> 2, qd = (idx & 3) * 4;
            int gr = row0 + r;
            float4 v = make_float4(0.f, 0.f, 0.f, 0.f);
            if (gr < M) v = *reinterpret_cast<const float4*>(A + (size_t)gr * K + k0 + qd);
            uint4 h, lo;
            split_tf32(v.x, h.x, lo.x);
            split_tf32(v.y, h.y, lo.y);
            split_tf32(v.z, h.z, lo.z);
            split_tf32(v.w, h.w, lo.w);
            *reinterpret_cast<uint4*>(&As_hi[r][qd]) = h;
            *reinterpret_cast<uint4*>(&As_lo[r][qd]) = lo;
        }
        // ---- load B tile 16x64 (1 float4 per thread), split, store [k][n] ----
        {
            int r = tid >> 4, c4 = (tid & 15) * 4;
            int gc = col0 + c4;
            float4 v = make_float4(0.f, 0.f, 0.f, 0.f);
            if (gc < N) v = *reinterpret_cast<const float4*>(B + (size_t)(k0 + r) * N + gc);
            uint4 h, lo;
            split_tf32(v.x, h.x, lo.x);
            split_tf32(v.y, h.y, lo.y);
            split_tf32(v.z, h.z, lo.z);
            split_tf32(v.w, h.w, lo.w);
            *reinterpret_cast<uint4*>(&Bs_hi[r][c4]) = h;
            *reinterpret_cast<uint4*>(&Bs_lo[r][c4]) = lo;
        }
        __syncthreads();

#pragma unroll
        for (int ks = 0; ks < 2; ks++) {
            int kk = ks * 8 + q;
            uint32_t a_h[2][4], a_l[2][4];
#pragma unroll
            for (int mt = 0; mt < 2; mt++) {
                int m0 = wm + mt * 16 + g;
                a_h[mt][0] = As_hi[m0][kk];
                a_h[mt][1] = As_hi[m0 + 8][kk];
                a_h[mt][2] = As_hi[m0][kk + 4];
                a_h[mt][3] = As_hi[m0 + 8][kk + 4];
                a_l[mt][0] = As_lo[m0][kk];
                a_l[mt][1] = As_lo[m0 + 8][kk];
                a_l[mt][2] = As_lo[m0][kk + 4];
                a_l[mt][3] = As_lo[m0 + 8][kk + 4];
            }
            uint32_t b_h[4][2], b_l[4][2];
#pragma unroll
            for (int nt = 0; nt < 4; nt++) {
                int n0 = wn + nt * 8 + g;
                b_h[nt][0] = Bs_hi[kk][n0];
                b_h[nt][1] = Bs_hi[kk + 4][n0];
                b_l[nt][0] = Bs_lo[kk][n0];
                b_l[nt][1] = Bs_lo[kk + 4][n0];
            }
#pragma unroll
            for (int mt = 0; mt < 2; mt++)
#pragma unroll
                for (int nt = 0; nt < 4; nt++) {
                    MMA_TF32(acc[mt][nt], a_h[mt], b_h[nt]);
                    MMA_TF32(acc[mt][nt], a_h[mt], b_l[nt]);
                    MMA_TF32(acc[mt][nt], a_l[mt], b_h[nt]);
                }
        }
        __syncthreads();
    }

    // ---- store C ----
#pragma unroll
    for (int mt = 0; mt < 2; mt++) {
#pragma unroll
        for (int nt = 0; nt < 4; nt++) {
            int r0 = row0 + wm + mt * 16 + g;
            int cc = col0 + wn + nt * 8 + 2 * q;
            if (cc < N) {
                if (r0 < M)
                    *reinterpret_cast<float2*>(Cmat + (size_t)r0 * N + cc) =
                        make_float2(acc[mt][nt][0], acc[mt][nt][1]);
                if (r0 + 8 < M)
                    *reinterpret_cast<float2*>(Cmat + (size_t)(r0 + 8) * N + cc) =
                        make_float2(acc[mt][nt][2], acc[mt][nt][3]);
            }
        }
    }
}

// ---------------- fused softmax + aggregation + bias + act ----------------
// out[n, c4..c4+3] = (sum_e exp(ev[e,h]) * h[src_e, c4..]) / (sum_e exp(ev[e,h])) + bias
// ev = leakyrelu(als[src] + ald[n]); exp(e)/sum(exp(e)) is shift-invariant and
// logits are O(1) here, so no max pass (overflow needs |e|>88).
template <int H, int C, int WPN, bool RELU>
__global__ void fused_agg_kernel(const float* __restrict__ hbuf,
                                 const float* __restrict__ bias,
                                 float* __restrict__ out) {
    const int HC = H * C, HCP = HC + 16, F4 = HC / 4;
    const int NPB = 8 / WPN;                      // nodes per 256-thread block
    int ws = threadIdx.x >> 5;
    int lane = threadIdx.x & 31;
    int n = blockIdx.x * NPB + ws / WPN;
    if (n >= NNODES) return;
    int idx = (ws % WPN) * 32 + lane;
    bool act = idx < F4;
    int c4 = min(idx * 4, HC - 4);
    int h = c4 / C;

    int st = g_offs[n], en = g_offs[n + 1];
    float aldn = hbuf[(size_t)n * HCP + HC + 8 + h];
    float4 bv = *reinterpret_cast<const float4*>(bias + c4);

    float ax = 0.f, ay = 0.f, az = 0.f, aw = 0.f, den = 0.f;
    int e = st;
    for (; e + 4 <= en; e += 4) {
        int s0 = g_csrsrc[e], s1 = g_csrsrc[e + 1], s2 = g_csrsrc[e + 2], s3 = g_csrsrc[e + 3];
        float l0 = hbuf[(size_t)s0 * HCP + HC + h];
        float l1 = hbuf[(size_t)s1 * HCP + HC + h];
        float l2 = hbuf[(size_t)s2 * HCP + HC + h];
        float l3 = hbuf[(size_t)s3 * HCP + HC + h];
        float4 v0 = *reinterpret_cast<const float4*>(hbuf + (size_t)s0 * HCP + c4);
        float4 v1 = *reinterpret_cast<const float4*>(hbuf + (size_t)s1 * HCP + c4);
        float4 v2 = *reinterpret_cast<const float4*>(hbuf + (size_t)s2 * HCP + c4);
        float4 v3 = *reinterpret_cast<const float4*>(hbuf + (size_t)s3 * HCP + c4);
        float e0 = l0 + aldn; e0 = (e0 >= 0.f) ? e0 : NEG_SLOPE * e0;
        float e1 = l1 + aldn; e1 = (e1 >= 0.f) ? e1 : NEG_SLOPE * e1;
        float e2 = l2 + aldn; e2 = (e2 >= 0.f) ? e2 : NEG_SLOPE * e2;
        float e3 = l3 + aldn; e3 = (e3 >= 0.f) ? e3 : NEG_SLOPE * e3;
        float a0 = __expf(e0);
        float a1 = __expf(e1);
        float a2 = __expf(e2);
        float a3 = __expf(e3);
        den += a0 + a1 + a2 + a3;
        ax += v0.x * a0 + v1.x * a1 + v2.x * a2 + v3.x * a3;
        ay += v0.y * a0 + v1.y * a1 + v2.y * a2 + v3.y * a3;
        az += v0.z * a0 + v1.z * a1 + v2.z * a2 + v3.z * a3;
        aw += v0.w * a0 + v1.w * a1 + v2.w * a2 + v3.w * a3;
    }
    for (; e < en; e++) {
        int s = g_csrsrc[e];
        float l = hbuf[(size_t)s * HCP + HC + h];
        float ev = l + aldn; ev = (ev >= 0.f) ? ev : NEG_SLOPE * ev;
        float a = __expf(ev);
        float4 v = *reinterpret_cast<const float4*>(hbuf + (size_t)s * HCP + c4);
        den += a;
        ax += v.x * a; ay += v.y * a; az += v.z * a; aw += v.w * a;
    }
    if (act) {
        float inv = 1.f / den;
        float4 r;
        r.x = ax * inv + bv.x;
        r.y = ay * inv + bv.y;
        r.z = az * inv + bv.z;
        r.w = aw * inv + bv.w;
        if (RELU) {
            r.x = fmaxf(r.x, 0.f); r.y = fmaxf(r.y, 0.f);
            r.z = fmaxf(r.z, 0.f); r.w = fmaxf(r.w, 0.f);
        }
        *reinterpret_cast<float4*>(out + (size_t)n * HC + c4) = r;
    }
}

// ---------------- host-side layer driver ----------------
template <int K, int H, int C, int WPN, bool RELU>
static void gat_layer(const float* xin, const float* W, const float* asrc, const float* adst,
                      const float* bias, float* hbuf, float* outbuf, float* Bp) {
    const int HC = H * C, HCP = HC + 16;
    pack_kernel<K, H, C><<<cdiv(K * HCP, 256), 256>>>(W, asrc, adst, Bp);
    dim3 gg(cdiv(HCP, 64), cdiv(NNODES, 128));
    gemm_tf32_kernel<<<gg, 256>>>(xin, Bp, hbuf, NNODES, K, HCP);
    const int NPB = 8 / WPN;
    fused_agg_kernel<H, C, WPN, RELU><<<cdiv(NNODES, NPB), 256>>>(hbuf, bias, outbuf);
}

extern "C" void kernel_launch(void* const* d_in, const int* in_sizes, int n_in,
                              void* d_out, int out_size) {
    const float* x      = (const float*)d_in[0];
    const int*   ei     = (const int*)d_in[1];
    const float* W1     = (const float*)d_in[2];
    const float* asrc1  = (const float*)d_in[3];
    const float* adst1  = (const float*)d_in[4];
    const float* b1     = (const float*)d_in[5];
    const float* W2     = (const float*)d_in[6];
    const float* asrc2  = (const float*)d_in[7];
    const float* adst2  = (const float*)d_in[8];
    const float* b2     = (const float*)d_in[9];
    const float* W3     = (const float*)d_in[10];
    const float* asrc3  = (const float*)d_in[11];
    const float* adst3  = (const float*)d_in[12];
    const float* b3     = (const float*)d_in[13];
    float* out = (float*)d_out;

    float *bufX, *bufH, *Bp;
    cudaGetSymbolAddress((void**)&bufX, g_bufX);
    cudaGetSymbolAddress((void**)&bufH, g_bufH);
    cudaGetSymbolAddress((void**)&Bp,   g_Bp);

    detect_kernel<<<1, 256>>>(ei);
    zero_deg_kernel<<<cdiv(NNODES, 256), 256>>>();
    convert_hist_kernel<<<cdiv(ETOT, 256), 256>>>(ei);
    scan_phase1_kernel<<<NSCAN_BLK, 256>>>();
    scan_phase2_kernel<<<1, 256>>>();
    scan_phase3_kernel<<<NSCAN_BLK, 256>>>();
    scatter_kernel<<<cdiv(ETOT, 256), 256>>>();

    // Layer 1: 128 -> 7x16 (relu)
    gat_layer<128, 7, 16, 1, true>(x, W1, asrc1, adst1, b1, bufH, bufX, Bp);
    // Layer 2: 112 -> 6x16 (relu)
    gat_layer<112, 6, 16, 1, true>(bufX, W2, asrc2, adst2, b2, bufH, bufX, Bp);
    // Layer 3: 96 -> 6x40, no relu, straight into d_out
    gat_layer<96, 6, 40, 2, false>(bufX, W3, asrc3, adst3, b3, bufH, out, Bp);
}

// round 13
// speedup vs baseline: 1.3010x; 1.3010x over previous
#include <cuda_runtime.h>
#include <cstdint>

#define NNODES 50000
#define ERAW   800000
#define ETOT   850000
#define NEG_SLOPE 0.2f
#define NSCAN_BLK 196            // ceil(50000/256)

// Layer dims (HCP = HC + 16 extra cols: [h(HC) | als(8) | ald(8)]):
//  L1: K=128 H=7 C=16 HC=112 HCP=128
//  L2: K=112 H=6 C=16 HC=96  HCP=112
//  L3: K=96  H=6 C=40 HC=240 HCP=256

// ---------------- scratch (device globals; no allocation allowed) ----------------
__device__ float g_bufX[(size_t)NNODES * 112];   // dense layer output / next input
__device__ float g_bufH[(size_t)NNODES * 256];   // GEMM output rows [h|als|ald]
__device__ float g_Bp  [24576];                  // packed B' (max 96*256)
__device__ int   g_edges[2 * ERAW];
__device__ int   g_deg   [NNODES];
__device__ int   g_offs  [NNODES + 1];
__device__ int   g_cursor[NNODES];
__device__ int   g_csrsrc[ETOT];
__device__ int   g_bsum  [NSCAN_BLK];
__device__ int   g_boff  [NSCAN_BLK];
__device__ int   g_is64;

static inline int cdiv(int a, int b) { return (a + b - 1) / b; }

// ---------------- edge-index width detect ----------------
__global__ void detect_kernel(const int* __restrict__ ei) {
    __shared__ int any;
    if (threadIdx.x == 0) any = 0;
    __syncthreads();
    int bad = 0;
    for (int i = threadIdx.x; i < 2048; i += blockDim.x)
        if (ei[2 * i + 1] != 0) bad = 1;
    if (bad) any = 1;
    __syncthreads();
    if (threadIdx.x == 0) g_is64 = any ? 0 : 1;
}

__global__ void zero_deg_kernel() {
    int i = blockIdx.x * blockDim.x + threadIdx.x;
    if (i < NNODES) g_deg[i] = 0;
}

// convert + histogram in one edge pass
__global__ void convert_hist_kernel(const int* __restrict__ ei) {
    int e = blockIdx.x * blockDim.x + threadIdx.x;
    if (e >= ETOT) return;
    int d;
    if (e < ERAW) {
        int s = g_is64 ? ei[2 * e] : ei[e];
        d     = g_is64 ? ei[2 * (ERAW + e)] : ei[ERAW + e];
        g_edges[e] = s;
        g_edges[ERAW + e] = d;
    } else {
        d = e - ERAW;
    }
    atomicAdd(&g_deg[d], 1);
}

// ---------------- multi-block exclusive scan of g_deg -> g_offs ----------------
__global__ void scan_phase1_kernel() {      // grid = NSCAN_BLK, block = 256
    __shared__ int sh[8];
    int i = blockIdx.x * 256 + threadIdx.x;
    int v = (i < NNODES) ? g_deg[i] : 0;
#pragma unroll
    for (int off = 16; off >= 1; off >>= 1) v += __shfl_xor_sync(0xffffffffu, v, off);
    if ((threadIdx.x & 31) == 0) sh[threadIdx.x >> 5] = v;
    __syncthreads();
    if (threadIdx.x == 0) {
        int s = 0;
#pragma unroll
        for (int w = 0; w < 8; w++) s += sh[w];
        g_bsum[blockIdx.x] = s;
    }
}

__global__ void scan_phase2_kernel() {      // 1 block, 256 threads
    __shared__ int sh[256];
    int t = threadIdx.x;
    int v = (t < NSCAN_BLK) ? g_bsum[t] : 0;
    sh[t] = v;
    __syncthreads();
    for (int off = 1; off < 256; off <<= 1) {
        int u = (t >= off) ? sh[t - off] : 0;
        __syncthreads();
        sh[t] += u;
        __syncthreads();
    }
    if (t < NSCAN_BLK) g_boff[t] = sh[t] - v;   // exclusive
}

__global__ void scan_phase3_kernel() {      // grid = NSCAN_BLK, block = 256
    __shared__ int sh[256];
    int t = threadIdx.x;
    int i = blockIdx.x * 256 + t;
    int v = (i < NNODES) ? g_deg[i] : 0;
    sh[t] = v;
    __syncthreads();
    for (int off = 1; off < 256; off <<= 1) {
        int u = (t >= off) ? sh[t - off] : 0;
        __syncthreads();
        sh[t] += u;
        __syncthreads();
    }
    if (i < NNODES) {
        int o = g_boff[blockIdx.x] + sh[t] - v;  // exclusive
        g_offs[i] = o;
        g_cursor[i] = o;
    }
    if (i == NNODES - 1) g_offs[NNODES] = ETOT;
}

__global__ void scatter_kernel() {
    int e = blockIdx.x * blockDim.x + threadIdx.x;
    if (e >= ETOT) return;
    int s, d;
    if (e < ERAW) { s = g_edges[e]; d = g_edges[ERAW + e]; }
    else          { s = d = e - ERAW; }
    int pos = atomicAdd(&g_cursor[d], 1);
    g_csrsrc[pos] = s;
}

// ---------------- pack B' = [W | W*a_src | W*a_dst(pad to 8 each)] ----------------
template <int K, int H, int C>
__global__ void pack_kernel(const float* __restrict__ W, const float* __restrict__ as,
                            const float* __restrict__ ad, float* __restrict__ Bp) {
    const int HC = H * C, HCP = HC + 16;
    int idx = blockIdx.x * blockDim.x + threadIdx.x;
    if (idx >= K * HCP) return;
    int k = idx / HCP, col = idx - k * HCP;
    float v = 0.f;
    if (col < HC) {
        v = W[(size_t)k * HC + col];
    } else {
        int hc = col - HC;
        int h = hc & 7;
        const float* a = (hc < 8) ? as : ad;
        if (h < H) {
#pragma unroll 4
            for (int c = 0; c < C; c++)
                v += W[(size_t)k * HC + h * C + c] * a[h * C + c];
        }
    }
    Bp[idx] = v;
}

// ---------------- GEMM: C[M,N] = A[M,K] @ B[K,N], 64x128 tile, 8x8 micro ------------
// 128 threads: tx = tid&15 (n, 16*8=128 cols), ty = tid>>4 (m, 8*8=64 rows).
// Smem bytes per 64 FFMA = 64B -> 1.0 B/FFMA, at crossbar parity (128B/cyc vs
// 128 FFMA/cyc per SM). K must be a multiple of 16 (128/112/96 all are).
__global__ void __launch_bounds__(128) gemm_kernel(const float* __restrict__ A,
                                                   const float* __restrict__ B,
                                                   float* __restrict__ Cmat,
                                                   int M, int K, int N) {
    const int BM = 64, BN = 128, BK = 16;
    __shared__ float As[BK][BM + 4];    // [k][m], stride 68
    __shared__ float Bs[BK][BN + 4];    // [k][n], stride 132

    int tid = threadIdx.x;
    int tx = tid & 15, ty = tid >> 4;
    int row0 = blockIdx.y * BM;
    int col0 = blockIdx.x * BN;

    float acc[8][8];
#pragma unroll
    for (int i = 0; i < 8; i++)
#pragma unroll
        for (int j = 0; j < 8; j++) acc[i][j] = 0.f;

    for (int k0 = 0; k0 < K; k0 += BK) {
        // A tile 64x16: 2 float4 per thread, store transposed [k][m]
#pragma unroll
        for (int l = 0; l < 2; l++) {
            int idx = tid + l * 128;
            int r = idx >> 2, c4 = (idx & 3) * 4;
            int gr = row0 + r;
            float4 v = make_float4(0.f, 0.f, 0.f, 0.f);
            if (gr < M) v = *reinterpret_cast<const float4*>(A + (size_t)gr * K + k0 + c4);
            As[c4 + 0][r] = v.x;
            As[c4 + 1][r] = v.y;
            As[c4 + 2][r] = v.z;
            As[c4 + 3][r] = v.w;
        }
        // B tile 16x128: 4 float4 per thread, row-major [k][n]
#pragma unroll
        for (int l = 0; l < 4; l++) {
            int idx = tid + l * 128;
            int r = idx >> 5, c4 = (idx & 31) * 4;
            int gc = col0 + c4;
            float4 v = make_float4(0.f, 0.f, 0.f, 0.f);
            if (gc < N) v = *reinterpret_cast<const float4*>(B + (size_t)(k0 + r) * N + gc);
            *reinterpret_cast<float4*>(&Bs[r][c4]) = v;
        }
        __syncthreads();

#pragma unroll
        for (int k = 0; k < BK; k++) {
            float4 a0 = *reinterpret_cast<const float4*>(&As[k][ty * 8]);
            float4 a1 = *reinterpret_cast<const float4*>(&As[k][ty * 8 + 4]);
            float4 b0 = *reinterpret_cast<const float4*>(&Bs[k][tx * 8]);
            float4 b1 = *reinterpret_cast<const float4*>(&Bs[k][tx * 8 + 4]);
            float ar[8] = {a0.x, a0.y, a0.z, a0.w, a1.x, a1.y, a1.z, a1.w};
            float br[8] = {b0.x, b0.y, b0.z, b0.w, b1.x, b1.y, b1.z, b1.w};
#pragma unroll
            for (int i = 0; i < 8; i++)
#pragma unroll
                for (int j = 0; j < 8; j++)
                    acc[i][j] += ar[i] * br[j];
        }
        __syncthreads();
    }

#pragma unroll
    for (int i = 0; i < 8; i++) {
        int gr = row0 + ty * 8 + i;
        if (gr >= M) continue;
        int gc = col0 + tx * 8;
        if (gc < N) {
            *reinterpret_cast<float4*>(Cmat + (size_t)gr * N + gc) =
                make_float4(acc[i][0], acc[i][1], acc[i][2], acc[i][3]);
            *reinterpret_cast<float4*>(Cmat + (size_t)gr * N + gc + 4) =
                make_float4(acc[i][4], acc[i][5], acc[i][6], acc[i][7]);
        }
    }
}

// ---------------- fused softmax + aggregation + bias + act ----------------
// out[n, c4..c4+3] = (sum_e exp(ev[e,h]) * h[src_e, c4..]) / (sum_e exp(ev[e,h])) + bias
// ev = leakyrelu(als[src] + ald[n]); exp(e)/sum(exp(e)) is shift-invariant and
// logits are O(1) here, so no max pass (overflow needs |e|>88).
template <int H, int C, int WPN, bool RELU>
__global__ void fused_agg_kernel(const float* __restrict__ hbuf,
                                 const float* __restrict__ bias,
                                 float* __restrict__ out) {
    const int HC = H * C, HCP = HC + 16, F4 = HC / 4;
    const int NPB = 8 / WPN;                      // nodes per 256-thread block
    int ws = threadIdx.x >> 5;
    int lane = threadIdx.x & 31;
    int n = blockIdx.x * NPB + ws / WPN;
    if (n >= NNODES) return;
    int idx = (ws % WPN) * 32 + lane;
    bool act = idx < F4;
    int c4 = min(idx * 4, HC - 4);
    int h = c4 / C;

    int st = g_offs[n], en = g_offs[n + 1];
    float aldn = hbuf[(size_t)n * HCP + HC + 8 + h];
    float4 bv = *reinterpret_cast<const float4*>(bias + c4);

    float ax = 0.f, ay = 0.f, az = 0.f, aw = 0.f, den = 0.f;
    int e = st;
    for (; e + 4 <= en; e += 4) {
        int s0 = g_csrsrc[e], s1 = g_csrsrc[e + 1], s2 = g_csrsrc[e + 2], s3 = g_csrsrc[e + 3];
        float l0 = hbuf[(size_t)s0 * HCP + HC + h];
        float l1 = hbuf[(size_t)s1 * HCP + HC + h];
        float l2 = hbuf[(size_t)s2 * HCP + HC + h];
        float l3 = hbuf[(size_t)s3 * HCP + HC + h];
        float4 v0 = *reinterpret_cast<const float4*>(hbuf + (size_t)s0 * HCP + c4);
        float4 v1 = *reinterpret_cast<const float4*>(hbuf + (size_t)s1 * HCP + c4);
        float4 v2 = *reinterpret_cast<const float4*>(hbuf + (size_t)s2 * HCP + c4);
        float4 v3 = *reinterpret_cast<const float4*>(hbuf + (size_t)s3 * HCP + c4);
        float e0 = l0 + aldn; e0 = (e0 >= 0.f) ? e0 : NEG_SLOPE * e0;
        float e1 = l1 + aldn; e1 = (e1 >= 0.f) ? e1 : NEG_SLOPE * e1;
        float e2 = l2 + aldn; e2 = (e2 >= 0.f) ? e2 : NEG_SLOPE * e2;
        float e3 = l3 + aldn; e3 = (e3 >= 0.f) ? e3 : NEG_SLOPE * e3;
        float a0 = __expf(e0);
        float a1 = __expf(e1);
        float a2 = __expf(e2);
        float a3 = __expf(e3);
        den += a0 + a1 + a2 + a3;
        ax += v0.x * a0 + v1.x * a1 + v2.x * a2 + v3.x * a3;
        ay += v0.y * a0 + v1.y * a1 + v2.y * a2 + v3.y * a3;
        az += v0.z * a0 + v1.z * a1 + v2.z * a2 + v3.z * a3;
        aw += v0.w * a0 + v1.w * a1 + v2.w * a2 + v3.w * a3;
    }
    for (; e < en; e++) {
        int s = g_csrsrc[e];
        float l = hbuf[(size_t)s * HCP + HC + h];
        float ev = l + aldn; ev = (ev >= 0.f) ? ev : NEG_SLOPE * ev;
        float a = __expf(ev);
        float4 v = *reinterpret_cast<const float4*>(hbuf + (size_t)s * HCP + c4);
        den += a;
        ax += v.x * a; ay += v.y * a; az += v.z * a; aw += v.w * a;
    }
    if (act) {
        float inv = 1.f / den;
        float4 r;
        r.x = ax * inv + bv.x;
        r.y = ay * inv + bv.y;
        r.z = az * inv + bv.z;
        r.w = aw * inv + bv.w;
        if (RELU) {
            r.x = fmaxf(r.x, 0.f); r.y = fmaxf(r.y, 0.f);
            r.z = fmaxf(r.z, 0.f); r.w = fmaxf(r.w, 0.f);
        }
        *reinterpret_cast<float4*>(out + (size_t)n * HC + c4) = r;
    }
}

// ---------------- host-side layer driver ----------------
template <int K, int H, int C, int WPN, bool RELU>
static void gat_layer(const float* xin, const float* W, const float* asrc, const float* adst,
                      const float* bias, float* hbuf, float* outbuf, float* Bp) {
    const int HC = H * C, HCP = HC + 16;
    pack_kernel<K, H, C><<<cdiv(K * HCP, 256), 256>>>(W, asrc, adst, Bp);
    dim3 gg(cdiv(HCP, 128), cdiv(NNODES, 64));
    gemm_kernel<<<gg, 128>>>(xin, Bp, hbuf, NNODES, K, HCP);
    const int NPB = 8 / WPN;
    fused_agg_kernel<H, C, WPN, RELU><<<cdiv(NNODES, NPB), 256>>>(hbuf, bias, outbuf);
}

extern "C" void kernel_launch(void* const* d_in, const int* in_sizes, int n_in,
                              void* d_out, int out_size) {
    const float* x      = (const float*)d_in[0];
    const int*   ei     = (const int*)d_in[1];
    const float* W1     = (const float*)d_in[2];
    const float* asrc1  = (const float*)d_in[3];
    const float* adst1  = (const float*)d_in[4];
    const float* b1     = (const float*)d_in[5];
    const float* W2     = (const float*)d_in[6];
    const float* asrc2  = (const float*)d_in[7];
    const float* adst2  = (const float*)d_in[8];
    const float* b2     = (const float*)d_in[9];
    const float* W3     = (const float*)d_in[10];
    const float* asrc3  = (const float*)d_in[11];
    const float* adst3  = (const float*)d_in[12];
    const float* b3     = (const float*)d_in[13];
    float* out = (float*)d_out;

    float *bufX, *bufH, *Bp;
    cudaGetSymbolAddress((void**)&bufX, g_bufX);
    cudaGetSymbolAddress((void**)&bufH, g_bufH);
    cudaGetSymbolAddress((void**)&Bp,   g_Bp);

    detect_kernel<<<1, 256>>>(ei);
    zero_deg_kernel<<<cdiv(NNODES, 256), 256>>>();
    convert_hist_kernel<<<cdiv(ETOT, 256), 256>>>(ei);
    scan_phase1_kernel<<<NSCAN_BLK, 256>>>();
    scan_phase2_kernel<<<1, 256>>>();
    scan_phase3_kernel<<<NSCAN_BLK, 256>>>();
    scatter_kernel<<<cdiv(ETOT, 256), 256>>>();

    // Layer 1: 128 -> 7x16 (relu)
    gat_layer<128, 7, 16, 1, true>(x, W1, asrc1, adst1, b1, bufH, bufX, Bp);
    // Layer 2: 112 -> 6x16 (relu)
    gat_layer<112, 6, 16, 1, true>(bufX, W2, asrc2, adst2, b2, bufH, bufX, Bp);
    // Layer 3: 96 -> 6x40, no relu, straight into d_out
    gat_layer<96, 6, 40, 2, false>(bufX, W3, asrc3, adst3, b3, bufH, out, Bp);
}